// round 2
// baseline (speedup 1.0000x reference)
#include <cuda_runtime.h>
#include <math.h>

#define S_  40
#define B_  32
#define T_  60
#define H_  256
#define F_  64
#define DIN 320
#define OUTD 128
#define GH  1024   // 4*H

// ---------------- device scratch (no allocations allowed) ----------------
__device__ float g_sen[S_ * B_ * DIN];          // sen[s][b][0:320]
__device__ float g_XW[2][S_ * B_ * GH];         // per-dir input transform + biases
__device__ float g_h[2][2][H_][B_];             // double-buffered hidden, [k][b] layout
__device__ float g_hfinal[2][B_][H_];           // final h_f / h_b
__device__ int g_mask_u8;
__device__ unsigned g_bar_count = 0;
__device__ unsigned g_done = 0;

// ---------------- mask dtype detection ----------------
// bool may arrive as uint8 (numpy bool) or int32. In int32 little-endian 0/1,
// all bytes at index i%4!=0 are zero; in uint8 layout many are nonzero.
__global__ void detect_mask_kernel(const unsigned char* __restrict__ m, int n) {
    __shared__ int found;
    if (threadIdx.x == 0) found = 0;
    __syncthreads();
    for (int i = threadIdx.x; i < n; i += blockDim.x) {
        if ((i & 3) != 0 && m[i] != 0) { found = 1; break; }
    }
    __syncthreads();
    if (threadIdx.x == 0) g_mask_u8 = found;
}

// ---------------- stage 1: embedding gather + attention pooling + feature sum ----
// one CTA (256 threads) per (b, s); emb rows staged in dynamic smem
__global__ void stage1_kernel(const int* __restrict__ x,
                              const unsigned char* __restrict__ xmask,
                              const float* __restrict__ xfeat,
                              const float* __restrict__ emb,
                              const float* __restrict__ attn_w,
                              const float* __restrict__ attn_b) {
    extern __shared__ float sm[];
    float* e_s     = sm;             // [60][256]
    float* score_s = sm + T_ * H_;   // [64]
    float* alpha_s = score_s + 64;   // [64]

    int bs = blockIdx.x;
    int b = bs / S_, s = bs % S_;
    int tid = threadIdx.x, warp = tid >> 5, lane = tid & 31;
    int u8 = g_mask_u8;
    long base = (long)(b * S_ + s) * T_;
    float ab = attn_b[0];

    for (int t = warp; t < T_; t += 8) {
        int xi = x[base + t];
        long mi = base + t;
        unsigned char mv = u8 ? xmask[mi] : xmask[mi * 4];
        int valid = (mv == 0);
        float4 v0, v1;
        if (valid) {
            const float4* er = (const float4*)(emb + (long)xi * H_);
            v0 = er[lane]; v1 = er[lane + 32];
        } else {
            v0 = make_float4(0.f, 0.f, 0.f, 0.f); v1 = v0;
        }
        float4* ed = (float4*)(e_s + t * H_);
        ed[lane] = v0; ed[lane + 32] = v1;
        const float4* aw = (const float4*)attn_w;
        float4 w0 = aw[lane], w1 = aw[lane + 32];
        float p = v0.x*w0.x + v0.y*w0.y + v0.z*w0.z + v0.w*w0.w
                + v1.x*w1.x + v1.y*w1.y + v1.z*w1.z + v1.w*w1.w;
        #pragma unroll
        for (int o = 16; o; o >>= 1) p += __shfl_xor_sync(0xffffffffu, p, o);
        if (lane == 0) score_s[t] = valid ? (p + ab) : -1e30f;
    }
    __syncthreads();

    // softmax over tokens (warp 0); invalid sentence -> all alphas 0
    if (warp == 0) {
        float s0 = (lane < T_)      ? score_s[lane]      : -1e30f;
        float s1 = (lane + 32 < T_) ? score_s[lane + 32] : -1e30f;
        float mx = fmaxf(s0, s1);
        #pragma unroll
        for (int o = 16; o; o >>= 1) mx = fmaxf(mx, __shfl_xor_sync(0xffffffffu, mx, o));
        float e0 = (s0 > -1e29f) ? expf(s0 - mx) : 0.f;
        float e1 = (s1 > -1e29f) ? expf(s1 - mx) : 0.f;
        float sum = e0 + e1;
        #pragma unroll
        for (int o = 16; o; o >>= 1) sum += __shfl_xor_sync(0xffffffffu, sum, o);
        float inv = (mx > -1e29f) ? (1.f / sum) : 0.f;
        if (lane < T_)      alpha_s[lane]      = e0 * inv;
        if (lane + 32 < T_) alpha_s[lane + 32] = e1 * inv;
    }
    __syncthreads();

    // emb_part: thread = hidden index
    float acc = 0.f;
    #pragma unroll 4
    for (int t = 0; t < T_; t++) acc += alpha_s[t] * e_s[t * H_ + tid];
    g_sen[(s * B_ + b) * DIN + tid] = acc;

    // feat_part: sum of valid token features
    if (tid < F_) {
        float fa = 0.f;
        const float* fp = xfeat + base * F_ + tid;
        #pragma unroll 4
        for (int t = 0; t < T_; t++)
            if (score_s[t] > -1e29f) fa += fp[t * F_];
        g_sen[(s * B_ + b) * DIN + H_ + tid] = fa;
    }
}

// ---------------- XW GEMM: XW[dir][m][n] = sen[m]·wih[n] + bih[n] + bhh[n] ----
// M=1280, N=1024, K=320; BM=BN=64, BK=32, 256 threads, 4x4 per thread
__global__ void __launch_bounds__(256) xw_gemm_kernel(
    const float* __restrict__ wf, const float* __restrict__ wb,
    const float* __restrict__ bih_f, const float* __restrict__ bhh_f,
    const float* __restrict__ bih_b, const float* __restrict__ bhh_b) {
    const int PAD = 33;
    __shared__ float As[64 * PAD];
    __shared__ float Bs[64 * PAD];
    int dir = blockIdx.z;
    const float* A  = g_sen;
    const float* W  = dir ? wb : wf;
    const float* b1 = dir ? bih_b : bih_f;
    const float* b2 = dir ? bhh_b : bhh_f;
    int m0 = blockIdx.x * 64, n0 = blockIdx.y * 64;
    int tid = threadIdx.x;
    int tx = tid & 15, ty = tid >> 4;
    float acc[4][4];
    #pragma unroll
    for (int i = 0; i < 4; i++)
        #pragma unroll
        for (int j = 0; j < 4; j++) acc[i][j] = 0.f;

    for (int kt = 0; kt < DIN; kt += 32) {
        #pragma unroll
        for (int l = 0; l < 2; l++) {
            int f4 = tid + l * 256;
            int r = f4 >> 3, k4 = f4 & 7;
            float4 va = *(const float4*)(A + (long)(m0 + r) * DIN + kt + k4 * 4);
            float4 vb = *(const float4*)(W + (long)(n0 + r) * DIN + kt + k4 * 4);
            int so = r * PAD + k4 * 4;
            As[so] = va.x; As[so + 1] = va.y; As[so + 2] = va.z; As[so + 3] = va.w;
            Bs[so] = vb.x; Bs[so + 1] = vb.y; Bs[so + 2] = vb.z; Bs[so + 3] = vb.w;
        }
        __syncthreads();
        #pragma unroll
        for (int kk = 0; kk < 32; kk++) {
            float a[4], bv[4];
            #pragma unroll
            for (int i = 0; i < 4; i++) a[i] = As[(ty + 16 * i) * PAD + kk];
            #pragma unroll
            for (int j = 0; j < 4; j++) bv[j] = Bs[(tx + 16 * j) * PAD + kk];
            #pragma unroll
            for (int i = 0; i < 4; i++)
                #pragma unroll
                for (int j = 0; j < 4; j++) acc[i][j] += a[i] * bv[j];
        }
        __syncthreads();
    }
    float* C = g_XW[dir];
    #pragma unroll
    for (int i = 0; i < 4; i++) {
        int m = m0 + ty + 16 * i;
        #pragma unroll
        for (int j = 0; j < 4; j++) {
            int n = n0 + tx + 16 * j;
            C[(long)m * GH + n] = acc[i][j] + b1[n] + b2[n];
        }
    }
}

// ---------------- persistent bidirectional LSTM recurrence ----------------
__device__ __forceinline__ float sigf(float x) { return 1.f / (1.f + expf(-x)); }

__device__ __forceinline__ void gridbar(unsigned gen) {
    __threadfence();
    __syncthreads();
    if (threadIdx.x == 0) {
        atomicAdd(&g_bar_count, 1u);
        while (*(volatile unsigned*)&g_bar_count < gen * 128u) { }
    }
    __syncthreads();
}

// grid: 128 CTAs (64 per direction), 256 threads.
// CTA owns 4 hidden units (16 gate rows). c lives in smem across steps.
__global__ void __launch_bounds__(256, 1) lstm_kernel(
    const float* __restrict__ whh_f, const float* __restrict__ whh_b,
    const int* __restrict__ lens) {
    extern __shared__ float sm[];
    float* w_s = sm;              // [16][256]
    float* h_s = sm + 16 * 256;   // [256][32]
    float* g_s = h_s + 256 * 32;  // [16][32]
    float* c_s = g_s + 16 * 32;   // [4][32]

    int dir = blockIdx.x >> 6;
    int cid = blockIdx.x & 63;
    int hh0 = cid * 4;
    int tid = threadIdx.x;
    const float* whh = dir ? whh_b : whh_f;

    for (int i = tid; i < 16 * 256; i += 256) {
        int lr = i >> 8, k = i & 255;
        int gate = lr >> 2, hl = lr & 3;
        w_s[lr * 256 + k] = whh[(gate * H_ + hh0 + hl) * H_ + k];
    }
    if (tid < 128) {
        c_s[tid] = 0.f;
        g_h[dir][0][hh0 + (tid >> 5)][tid & 31] = 0.f;
    }
    int myb = tid & 31;
    int lenb = lens[myb];
    gridbar(1);

    int r = tid >> 5;  // warp id = gate-row offset (rows r and r+8)
    const float* XWd = g_XW[dir];

    for (int step = 0; step < S_; step++) {
        int s = dir ? (S_ - 1 - step) : step;
        int p = step & 1;
        // stage full h_prev into smem; must bypass L1 (written by peer CTAs)
        const float4* hsrc = (const float4*)g_h[dir][p];
        float4* hdst = (float4*)h_s;
        #pragma unroll
        for (int i = 0; i < 8; i++) hdst[tid + i * 256] = __ldcv(hsrc + tid + i * 256);
        // prefetch input-transform terms
        int lr0 = r, lr1 = r + 8;
        float xw0 = XWd[(long)(s * B_ + myb) * GH + ((lr0 >> 2) * H_ + hh0 + (lr0 & 3))];
        float xw1 = XWd[(long)(s * B_ + myb) * GH + ((lr1 >> 2) * H_ + hh0 + (lr1 & 3))];
        __syncthreads();

        float acc0 = 0.f, acc1 = 0.f;
        const float* w0 = w_s + lr0 * 256;
        const float* w1 = w_s + lr1 * 256;
        #pragma unroll 4
        for (int k = 0; k < H_; k += 4) {
            float4 wa = *(const float4*)(w0 + k);
            float4 wb = *(const float4*)(w1 + k);
            float h0 = h_s[k * 32 + myb];
            float h1 = h_s[(k + 1) * 32 + myb];
            float h2 = h_s[(k + 2) * 32 + myb];
            float h3 = h_s[(k + 3) * 32 + myb];
            acc0 += wa.x * h0; acc1 += wb.x * h0;
            acc0 += wa.y * h1; acc1 += wb.y * h1;
            acc0 += wa.z * h2; acc1 += wb.z * h2;
            acc0 += wa.w * h3; acc1 += wb.w * h3;
        }
        g_s[lr0 * 32 + myb] = acc0 + xw0;
        g_s[lr1 * 32 + myb] = acc1 + xw1;
        __syncthreads();

        if (tid < 128) {
            int hl = tid >> 5;
            float gi = g_s[(0 * 4 + hl) * 32 + myb];
            float gf = g_s[(1 * 4 + hl) * 32 + myb];
            float gg = g_s[(2 * 4 + hl) * 32 + myb];
            float go = g_s[(3 * 4 + hl) * 32 + myb];
            float c  = c_s[hl * 32 + myb];
            float c2 = sigf(gf) * c + sigf(gi) * tanhf(gg);
            float h2v = sigf(go) * tanhf(c2);
            bool upd = (s < lenb);
            float hn;
            if (upd) { c_s[hl * 32 + myb] = c2; hn = h2v; }
            else     { hn = h_s[(hh0 + hl) * 32 + myb]; }
            g_h[dir][p ^ 1][hh0 + hl][myb] = hn;
            if (step == S_ - 1) g_hfinal[dir][myb][hh0 + hl] = hn;
        }
        gridbar(step + 2);
    }

    // reset barrier state for the next (graph-replayed) launch
    __syncthreads();
    if (tid == 0) {
        unsigned prev = atomicAdd(&g_done, 1u);
        if (prev == 127u) { g_bar_count = 0u; g_done = 0u; __threadfence(); }
    }
}

// ---------------- FC + BN(batch axis) + relu + log_softmax(batch axis) ----
// Replicates stack([h_f,h_b],0).reshape(B, 2H):
//   hidden[i][d] = hfinal[i>>4][2*(i&15) + (d>>8)][d&255]
__global__ void final_kernel(const float* __restrict__ fc_w, const float* __restrict__ fc_b,
                             const float* __restrict__ gamma, const float* __restrict__ beta,
                             float* __restrict__ out) {
    __shared__ float wsh[2 * H_];
    __shared__ float lg[B_];
    int j = blockIdx.x;
    int tid = threadIdx.x, warp = tid >> 5, lane = tid & 31;
    for (int i = tid; i < 2 * H_; i += 256) wsh[i] = fc_w[j * 2 * H_ + i];
    __syncthreads();

    #pragma unroll
    for (int ii = 0; ii < 4; ii++) {
        int i = warp * 4 + ii;
        int dirc = i >> 4;
        int bb = (i & 15) * 2;
        const float* h0 = g_hfinal[dirc][bb];
        const float* h1 = g_hfinal[dirc][bb + 1];
        float p = 0.f;
        for (int k = lane; k < H_; k += 32) p += h0[k] * wsh[k] + h1[k] * wsh[H_ + k];
        #pragma unroll
        for (int o = 16; o; o >>= 1) p += __shfl_xor_sync(0xffffffffu, p, o);
        if (lane == 0) lg[i] = p + fc_b[j];
    }
    __syncthreads();

    if (warp == 0) {
        float v = lg[lane];
        float sum = v;
        #pragma unroll
        for (int o = 16; o; o >>= 1) sum += __shfl_xor_sync(0xffffffffu, sum, o);
        float mu = sum * (1.f / 32.f);
        float d = v - mu;
        float vs = d * d;
        #pragma unroll
        for (int o = 16; o; o >>= 1) vs += __shfl_xor_sync(0xffffffffu, vs, o);
        float var = vs * (1.f / 32.f);
        float y = gamma[j] * d * rsqrtf(var + 1e-5f) + beta[j];
        y = fmaxf(y, 0.f);
        float mx = y;
        #pragma unroll
        for (int o = 16; o; o >>= 1) mx = fmaxf(mx, __shfl_xor_sync(0xffffffffu, mx, o));
        float ev = expf(y - mx);
        float se = ev;
        #pragma unroll
        for (int o = 16; o; o >>= 1) se += __shfl_xor_sync(0xffffffffu, se, o);
        out[lane * OUTD + j] = y - mx - logf(se);
    }
}

// ---------------- launch ----------------
extern "C" void kernel_launch(void* const* d_in, const int* in_sizes, int n_in,
                              void* d_out, int out_size) {
    const int*           x      = (const int*)d_in[0];
    const unsigned char* xmask  = (const unsigned char*)d_in[1];
    const float*         xfeat  = (const float*)d_in[2];
    const int*           lens   = (const int*)d_in[3];
    // d_in[4] clause, d_in[5] cls: unused
    const float* emb    = (const float*)d_in[6];
    const float* attn_w = (const float*)d_in[7];
    const float* attn_b = (const float*)d_in[8];
    const float* wih_f  = (const float*)d_in[9];
    const float* whh_f  = (const float*)d_in[10];
    const float* bih_f  = (const float*)d_in[11];
    const float* bhh_f  = (const float*)d_in[12];
    const float* wih_b  = (const float*)d_in[13];
    const float* whh_b  = (const float*)d_in[14];
    const float* bih_b  = (const float*)d_in[15];
    const float* bhh_b  = (const float*)d_in[16];
    const float* fc_w   = (const float*)d_in[17];
    const float* fc_b   = (const float*)d_in[18];
    const float* bn_g   = (const float*)d_in[19];
    const float* bn_b   = (const float*)d_in[20];

    const int smem1 = (T_ * H_ + 128) * 4;                       // ~62 KB
    const int smemL = (16 * 256 + 256 * 32 + 16 * 32 + 128) * 4; // ~52 KB
    cudaFuncSetAttribute(stage1_kernel, cudaFuncAttributeMaxDynamicSharedMemorySize, smem1);
    cudaFuncSetAttribute(lstm_kernel,   cudaFuncAttributeMaxDynamicSharedMemorySize, smemL);

    detect_mask_kernel<<<1, 256>>>(xmask, B_ * S_ * T_);
    stage1_kernel<<<B_ * S_, 256, smem1>>>(x, xmask, xfeat, emb, attn_w, attn_b);
    xw_gemm_kernel<<<dim3(S_ * B_ / 64, GH / 64, 2), 256>>>(wih_f, wih_b, bih_f, bhh_f, bih_b, bhh_b);
    lstm_kernel<<<128, 256, smemL>>>(whh_f, whh_b, lens);
    final_kernel<<<OUTD, 256>>>(fc_w, fc_b, bn_g, bn_b, (float*)d_out);
}

// round 3
// speedup vs baseline: 1.3595x; 1.3595x over previous
#include <cuda_runtime.h>
#include <math.h>

#define S_  40
#define B_  32
#define T_  60
#define H_  256
#define F_  64
#define DIN 320
#define OUTD 128
#define GH  1024   // 4*H

// ---------------- device scratch ----------------
__device__ float g_sen[B_ * S_ * DIN];          // sen[b][s][0:320]
__device__ float g_XW[2][B_ * S_ * GH];         // [dir][b*S+s][1024]
__device__ float g_h2[2][2][B_][H_];            // double-buffered hidden, [b][k]
__device__ float g_hfinal[2][B_][H_];
__device__ int g_mask_u8;
__device__ unsigned g_bar_count = 0;
__device__ unsigned g_done = 0;

// ---------------- mask dtype detection (vectorized) ----------------
// int32 little-endian 0/1 words never have bytes 1..3 set; uint8 layout does.
__global__ void detect_mask_kernel(const uint4* __restrict__ m, int nwords4) {
    __shared__ int found;
    if (threadIdx.x == 0) found = 0;
    __syncthreads();
    for (int i = threadIdx.x; i < nwords4; i += blockDim.x) {
        uint4 v = m[i];
        if ((v.x | v.y | v.z | v.w) & 0xFFFFFF00u) { found = 1; break; }
    }
    __syncthreads();
    if (threadIdx.x == 0) g_mask_u8 = found;
}

// ---------------- stage 1: gather + attention pooling + feature sum ----
__global__ void stage1_kernel(const int* __restrict__ x,
                              const unsigned char* __restrict__ xmask,
                              const float* __restrict__ xfeat,
                              const float* __restrict__ emb,
                              const float* __restrict__ attn_w,
                              const float* __restrict__ attn_b) {
    extern __shared__ float sm[];
    float* e_s     = sm;             // [60][256]
    float* score_s = sm + T_ * H_;   // [64]
    float* alpha_s = score_s + 64;   // [64]

    int bs = blockIdx.x;
    int b = bs / S_, s = bs % S_;
    int tid = threadIdx.x, warp = tid >> 5, lane = tid & 31;
    int u8 = g_mask_u8;
    long base = (long)(b * S_ + s) * T_;
    float ab = attn_b[0];

    for (int t = warp; t < T_; t += 8) {
        int xi = x[base + t];
        long mi = base + t;
        unsigned char mv = u8 ? xmask[mi] : xmask[mi * 4];
        int valid = (mv == 0);
        float4 v0, v1;
        if (valid) {
            const float4* er = (const float4*)(emb + (long)xi * H_);
            v0 = er[lane]; v1 = er[lane + 32];
        } else {
            v0 = make_float4(0.f, 0.f, 0.f, 0.f); v1 = v0;
        }
        float4* ed = (float4*)(e_s + t * H_);
        ed[lane] = v0; ed[lane + 32] = v1;
        const float4* aw = (const float4*)attn_w;
        float4 w0 = aw[lane], w1 = aw[lane + 32];
        float p = v0.x*w0.x + v0.y*w0.y + v0.z*w0.z + v0.w*w0.w
                + v1.x*w1.x + v1.y*w1.y + v1.z*w1.z + v1.w*w1.w;
        #pragma unroll
        for (int o = 16; o; o >>= 1) p += __shfl_xor_sync(0xffffffffu, p, o);
        if (lane == 0) score_s[t] = valid ? (p + ab) : -1e30f;
    }
    __syncthreads();

    if (warp == 0) {
        float s0 = (lane < T_)      ? score_s[lane]      : -1e30f;
        float s1 = (lane + 32 < T_) ? score_s[lane + 32] : -1e30f;
        float mx = fmaxf(s0, s1);
        #pragma unroll
        for (int o = 16; o; o >>= 1) mx = fmaxf(mx, __shfl_xor_sync(0xffffffffu, mx, o));
        float e0 = (s0 > -1e29f) ? expf(s0 - mx) : 0.f;
        float e1 = (s1 > -1e29f) ? expf(s1 - mx) : 0.f;
        float sum = e0 + e1;
        #pragma unroll
        for (int o = 16; o; o >>= 1) sum += __shfl_xor_sync(0xffffffffu, sum, o);
        float inv = (mx > -1e29f) ? (1.f / sum) : 0.f;
        if (lane < T_)      alpha_s[lane]      = e0 * inv;
        if (lane + 32 < T_) alpha_s[lane + 32] = e1 * inv;
    }
    __syncthreads();

    float acc = 0.f;
    #pragma unroll 4
    for (int t = 0; t < T_; t++) acc += alpha_s[t] * e_s[t * H_ + tid];
    g_sen[(b * S_ + s) * DIN + tid] = acc;   // [b][s] layout

    if (tid < F_) {
        float fa = 0.f;
        const float* fp = xfeat + base * F_ + tid;
        #pragma unroll 4
        for (int t = 0; t < T_; t++)
            if (score_s[t] > -1e29f) fa += fp[t * F_];
        g_sen[(b * S_ + s) * DIN + H_ + tid] = fa;
    }
}

// ---------------- XW GEMM with early-exit of padded M-tiles ----------------
// XW[dir][m][n] = sen[m]·wih[n] + bih[n] + bhh[n],  m = b*S + s
__global__ void __launch_bounds__(256) xw_gemm_kernel(
    const float* __restrict__ wf, const float* __restrict__ wb,
    const float* __restrict__ bih_f, const float* __restrict__ bhh_f,
    const float* __restrict__ bih_b, const float* __restrict__ bhh_b,
    const int* __restrict__ lens) {
    int m0 = blockIdx.x * 64;
    // skip tiles whose rows are all padding (values never read by lstm)
    {
        bool act = false;
        #pragma unroll 8
        for (int mm = 0; mm < 64; mm++) {
            int m = m0 + mm;
            if ((m % S_) < lens[m / S_]) { act = true; break; }
        }
        if (!act) return;
    }
    const int PAD = 33;
    __shared__ float As[64 * PAD];
    __shared__ float Bs[64 * PAD];
    int dir = blockIdx.z;
    const float* A  = g_sen;
    const float* W  = dir ? wb : wf;
    const float* b1 = dir ? bih_b : bih_f;
    const float* b2 = dir ? bhh_b : bhh_f;
    int n0 = blockIdx.y * 64;
    int tid = threadIdx.x;
    int tx = tid & 15, ty = tid >> 4;
    float acc[4][4];
    #pragma unroll
    for (int i = 0; i < 4; i++)
        #pragma unroll
        for (int j = 0; j < 4; j++) acc[i][j] = 0.f;

    for (int kt = 0; kt < DIN; kt += 32) {
        #pragma unroll
        for (int l = 0; l < 2; l++) {
            int f4 = tid + l * 256;
            int r = f4 >> 3, k4 = f4 & 7;
            float4 va = *(const float4*)(A + (long)(m0 + r) * DIN + kt + k4 * 4);
            float4 vb = *(const float4*)(W + (long)(n0 + r) * DIN + kt + k4 * 4);
            int so = r * PAD + k4 * 4;
            As[so] = va.x; As[so + 1] = va.y; As[so + 2] = va.z; As[so + 3] = va.w;
            Bs[so] = vb.x; Bs[so + 1] = vb.y; Bs[so + 2] = vb.z; Bs[so + 3] = vb.w;
        }
        __syncthreads();
        #pragma unroll
        for (int kk = 0; kk < 32; kk++) {
            float a[4], bv[4];
            #pragma unroll
            for (int i = 0; i < 4; i++) a[i] = As[(ty + 16 * i) * PAD + kk];
            #pragma unroll
            for (int j = 0; j < 4; j++) bv[j] = Bs[(tx + 16 * j) * PAD + kk];
            #pragma unroll
            for (int i = 0; i < 4; i++)
                #pragma unroll
                for (int j = 0; j < 4; j++) acc[i][j] += a[i] * bv[j];
        }
        __syncthreads();
    }
    float* C = g_XW[dir];
    #pragma unroll
    for (int i = 0; i < 4; i++) {
        int m = m0 + ty + 16 * i;
        #pragma unroll
        for (int j = 0; j < 4; j++) {
            int n = n0 + tx + 16 * j;
            C[(long)m * GH + n] = acc[i][j] + b1[n] + b2[n];
        }
    }
}

// ---------------- persistent bidirectional LSTM recurrence ----------------
__device__ __forceinline__ float sigf(float x) { return 1.f / (1.f + expf(-x)); }

__device__ __forceinline__ void gridbar(unsigned gen) {
    __threadfence();
    __syncthreads();
    if (threadIdx.x == 0) {
        atomicAdd(&g_bar_count, 1u);
        while (*(volatile unsigned*)&g_bar_count < gen * 128u) { }
    }
    __syncthreads();
}

// 128 CTAs (64/dir), 256 threads. CTA = 4 hidden units (16 gate rows) x 32 batch.
// Warp w owns batch-quad [4w,4w+4); lane = (khalf, row): rows 0..15, K split 2x128.
// h in smem as [b][k] -> all h reads are warp-broadcast float4.
__global__ void __launch_bounds__(256, 1) lstm_kernel(
    const float* __restrict__ whh_f, const float* __restrict__ whh_b,
    const int* __restrict__ lens) {
    extern __shared__ float sm[];
    float* w_s = sm;               // [16][260] padded
    float* h_s = sm + 16 * 260;    // [32][256]
    float* g_s = h_s + 32 * 256;   // [16][33] padded
    float* c_s = g_s + 16 * 33;    // [4][32]

    int dir = blockIdx.x >> 6;
    int cid = blockIdx.x & 63;
    int hh0 = cid * 4;
    int tid = threadIdx.x;
    const float* whh = dir ? whh_b : whh_f;

    for (int i = tid; i < 16 * 256; i += 256) {
        int lr = i >> 8, k = i & 255;
        int gate = lr >> 2, hl = lr & 3;
        w_s[lr * 260 + k] = whh[(gate * H_ + hh0 + hl) * H_ + k];
    }
    if (tid < 128) {
        c_s[tid] = 0.f;
        int hl = tid >> 5, b = tid & 31;
        g_h2[dir][0][b][hh0 + hl] = 0.f;
    }
    int lane = tid & 31, wrp = tid >> 5;
    int lr = lane & 15, khalf = lane >> 4;
    int b0 = wrp * 4;
    int grow = (lr >> 2) * H_ + hh0 + (lr & 3);
    int len_q = lens[b0];          // quad max (lens sorted descending)
    int lenb = lens[lane];         // per-batch len (epilogue uses b = tid&31)
    const float* XWd = g_XW[dir];
    gridbar(1);

    for (int step = 0; step < S_; step++) {
        int s = dir ? (S_ - 1 - step) : step;
        int p = step & 1;
        // stage full h_prev [b][k] into smem (bypass L1: peer-CTA writes)
        const float4* hsrc = (const float4*)&g_h2[dir][p][0][0];
        float4* hdst = (float4*)h_s;
        #pragma unroll
        for (int i = 0; i < 8; i++) hdst[tid + i * 256] = __ldcv(hsrc + tid + i * 256);
        // prefetch XW terms (independent of h -> hidden under staging latency)
        float xw0 = 0.f, xw1 = 0.f, xw2 = 0.f, xw3 = 0.f;
        if (khalf == 0) {
            long base = ((long)b0 * S_ + s) * GH + grow;
            xw0 = XWd[base];
            xw1 = XWd[base + (long)S_ * GH];
            xw2 = XWd[base + 2L * S_ * GH];
            xw3 = XWd[base + 3L * S_ * GH];
        }
        bool act = (s < len_q);    // warp-uniform
        __syncthreads();

        float a0 = 0.f, a1 = 0.f, a2 = 0.f, a3 = 0.f;
        if (act) {
            const float* wp = w_s + lr * 260 + khalf * 128;
            const float* hp = h_s + b0 * 256 + khalf * 128;
            #pragma unroll 8
            for (int k = 0; k < 128; k += 4) {
                float4 wv = *(const float4*)(wp + k);
                float4 h0 = *(const float4*)(hp + k);
                float4 h1 = *(const float4*)(hp + 256 + k);
                float4 h2 = *(const float4*)(hp + 512 + k);
                float4 h3 = *(const float4*)(hp + 768 + k);
                a0 += wv.x*h0.x + wv.y*h0.y + wv.z*h0.z + wv.w*h0.w;
                a1 += wv.x*h1.x + wv.y*h1.y + wv.z*h1.z + wv.w*h1.w;
                a2 += wv.x*h2.x + wv.y*h2.y + wv.z*h2.z + wv.w*h2.w;
                a3 += wv.x*h3.x + wv.y*h3.y + wv.z*h3.z + wv.w*h3.w;
            }
            a0 += __shfl_xor_sync(0xffffffffu, a0, 16);
            a1 += __shfl_xor_sync(0xffffffffu, a1, 16);
            a2 += __shfl_xor_sync(0xffffffffu, a2, 16);
            a3 += __shfl_xor_sync(0xffffffffu, a3, 16);
            if (khalf == 0) {
                g_s[lr * 33 + b0 + 0] = a0 + xw0;
                g_s[lr * 33 + b0 + 1] = a1 + xw1;
                g_s[lr * 33 + b0 + 2] = a2 + xw2;
                g_s[lr * 33 + b0 + 3] = a3 + xw3;
            }
        }
        __syncthreads();

        if (tid < 128) {
            int hl = tid >> 5, b = tid & 31;
            float gi = g_s[(0 * 4 + hl) * 33 + b];
            float gf = g_s[(1 * 4 + hl) * 33 + b];
            float gg = g_s[(2 * 4 + hl) * 33 + b];
            float go = g_s[(3 * 4 + hl) * 33 + b];
            float c  = c_s[hl * 32 + b];
            float c2 = sigf(gf) * c + sigf(gi) * tanhf(gg);
            float h2v = sigf(go) * tanhf(c2);
            bool upd = (s < lenb);
            float hn;
            if (upd) { c_s[hl * 32 + b] = c2; hn = h2v; }
            else     { hn = h_s[b * 256 + hh0 + hl]; }
            g_h2[dir][p ^ 1][b][hh0 + hl] = hn;
            if (step == S_ - 1) g_hfinal[dir][b][hh0 + hl] = hn;
        }
        gridbar(step + 2);
    }

    __syncthreads();
    if (tid == 0) {
        unsigned prev = atomicAdd(&g_done, 1u);
        if (prev == 127u) { g_bar_count = 0u; g_done = 0u; __threadfence(); }
    }
}

// ---------------- FC + BN(batch axis) + relu + log_softmax(batch axis) ----
__global__ void final_kernel(const float* __restrict__ fc_w, const float* __restrict__ fc_b,
                             const float* __restrict__ gamma, const float* __restrict__ beta,
                             float* __restrict__ out) {
    __shared__ float wsh[2 * H_];
    __shared__ float lg[B_];
    int j = blockIdx.x;
    int tid = threadIdx.x, warp = tid >> 5, lane = tid & 31;
    for (int i = tid; i < 2 * H_; i += 256) wsh[i] = fc_w[j * 2 * H_ + i];
    __syncthreads();

    #pragma unroll
    for (int ii = 0; ii < 4; ii++) {
        int i = warp * 4 + ii;
        int dirc = i >> 4;
        int bb = (i & 15) * 2;
        const float* h0 = g_hfinal[dirc][bb];
        const float* h1 = g_hfinal[dirc][bb + 1];
        float p = 0.f;
        for (int k = lane; k < H_; k += 32) p += h0[k] * wsh[k] + h1[k] * wsh[H_ + k];
        #pragma unroll
        for (int o = 16; o; o >>= 1) p += __shfl_xor_sync(0xffffffffu, p, o);
        if (lane == 0) lg[i] = p + fc_b[j];
    }
    __syncthreads();

    if (warp == 0) {
        float v = lg[lane];
        float sum = v;
        #pragma unroll
        for (int o = 16; o; o >>= 1) sum += __shfl_xor_sync(0xffffffffu, sum, o);
        float mu = sum * (1.f / 32.f);
        float d = v - mu;
        float vs = d * d;
        #pragma unroll
        for (int o = 16; o; o >>= 1) vs += __shfl_xor_sync(0xffffffffu, vs, o);
        float var = vs * (1.f / 32.f);
        float y = gamma[j] * d * rsqrtf(var + 1e-5f) + beta[j];
        y = fmaxf(y, 0.f);
        float mx = y;
        #pragma unroll
        for (int o = 16; o; o >>= 1) mx = fmaxf(mx, __shfl_xor_sync(0xffffffffu, mx, o));
        float ev = expf(y - mx);
        float se = ev;
        #pragma unroll
        for (int o = 16; o; o >>= 1) se += __shfl_xor_sync(0xffffffffu, se, o);
        out[lane * OUTD + j] = y - mx - logf(se);
    }
}

// ---------------- launch ----------------
extern "C" void kernel_launch(void* const* d_in, const int* in_sizes, int n_in,
                              void* d_out, int out_size) {
    const int*           x      = (const int*)d_in[0];
    const unsigned char* xmask  = (const unsigned char*)d_in[1];
    const float*         xfeat  = (const float*)d_in[2];
    const int*           lens   = (const int*)d_in[3];
    const float* emb    = (const float*)d_in[6];
    const float* attn_w = (const float*)d_in[7];
    const float* attn_b = (const float*)d_in[8];
    const float* wih_f  = (const float*)d_in[9];
    const float* whh_f  = (const float*)d_in[10];
    const float* bih_f  = (const float*)d_in[11];
    const float* bhh_f  = (const float*)d_in[12];
    const float* wih_b  = (const float*)d_in[13];
    const float* whh_b  = (const float*)d_in[14];
    const float* bih_b  = (const float*)d_in[15];
    const float* bhh_b  = (const float*)d_in[16];
    const float* fc_w   = (const float*)d_in[17];
    const float* fc_b   = (const float*)d_in[18];
    const float* bn_g   = (const float*)d_in[19];
    const float* bn_b   = (const float*)d_in[20];

    const int smem1 = (T_ * H_ + 128) * 4;
    const int smemL = (16 * 260 + 32 * 256 + 16 * 33 + 128) * 4;  // ~52 KB
    cudaFuncSetAttribute(stage1_kernel, cudaFuncAttributeMaxDynamicSharedMemorySize, smem1);
    cudaFuncSetAttribute(lstm_kernel,   cudaFuncAttributeMaxDynamicSharedMemorySize, smemL);

    detect_mask_kernel<<<1, 256>>>((const uint4*)xmask, (B_ * S_ * T_) / 16);
    stage1_kernel<<<B_ * S_, 256, smem1>>>(x, xmask, xfeat, emb, attn_w, attn_b);
    xw_gemm_kernel<<<dim3(B_ * S_ / 64, GH / 64, 2), 256>>>(wih_f, wih_b, bih_f, bhh_f,
                                                            bih_b, bhh_b, lens);
    lstm_kernel<<<128, 256, smemL>>>(whh_f, whh_b, lens);
    final_kernel<<<OUTD, 256>>>(fc_w, fc_b, bn_g, bn_b, (float*)d_out);
}

// round 4
// speedup vs baseline: 1.5250x; 1.1217x over previous
#include <cuda_runtime.h>
#include <math.h>
#include <stdint.h>

#define S_  40
#define B_  32
#define T_  60
#define H_  256
#define F_  64
#define DIN 320
#define OUTD 128
#define GH  1024   // 4*H
#define CLUSTER 8

// ---------------- device scratch ----------------
__device__ float g_sen[B_ * S_ * DIN];          // sen[b][s][0:320]
__device__ float g_XW[2][B_ * S_ * GH];         // [dir][b*S+s][1024]
__device__ float g_hfinal[2][B_][H_];
__device__ int g_mask_u8;

// ---------------- f32x2 helpers (Blackwell packed fp32) ----------------
__device__ __forceinline__ unsigned long long packf2(float a, float b) {
    unsigned long long r;
    asm("mov.b64 %0, {%1,%2};" : "=l"(r) : "f"(a), "f"(b));
    return r;
}
__device__ __forceinline__ unsigned long long fma2(unsigned long long a,
                                                   unsigned long long b,
                                                   unsigned long long c) {
    unsigned long long d;
    asm("fma.rn.f32x2 %0, %1, %2, %3;" : "=l"(d) : "l"(a), "l"(b), "l"(c));
    return d;
}
__device__ __forceinline__ unsigned long long addf2(unsigned long long a,
                                                    unsigned long long b) {
    unsigned long long d;
    asm("add.rn.f32x2 %0, %1, %2;" : "=l"(d) : "l"(a), "l"(b));
    return d;
}
__device__ __forceinline__ void unpackf2(unsigned long long v, float& lo, float& hi) {
    asm("mov.b64 {%0,%1}, %2;" : "=f"(lo), "=f"(hi) : "l"(v));
}

__device__ __forceinline__ uint32_t smem_u32(const void* p) {
    uint32_t a;
    asm("{ .reg .u64 t; cvta.to.shared.u64 t, %1; cvt.u32.u64 %0, t; }" : "=r"(a) : "l"(p));
    return a;
}
__device__ __forceinline__ uint32_t mapa_u32(uint32_t saddr, int rank) {
    uint32_t r;
    asm("mapa.shared::cluster.u32 %0, %1, %2;" : "=r"(r) : "r"(saddr), "r"(rank));
    return r;
}
__device__ __forceinline__ void st_cluster_f32(uint32_t addr, float v) {
    asm volatile("st.shared::cluster.f32 [%0], %1;" :: "r"(addr), "f"(v) : "memory");
}
#define CLUSTER_SYNC() do { \
    asm volatile("barrier.cluster.arrive.aligned;" ::: "memory"); \
    asm volatile("barrier.cluster.wait.aligned;" ::: "memory"); \
} while (0)

// ---------------- mask dtype detection ----------------
__global__ void detect_mask_kernel(const uint4* __restrict__ m, int nwords4) {
    __shared__ int found;
    if (threadIdx.x == 0) found = 0;
    __syncthreads();
    for (int i = threadIdx.x; i < nwords4; i += blockDim.x) {
        uint4 v = m[i];
        if ((v.x | v.y | v.z | v.w) & 0xFFFFFF00u) { found = 1; break; }
    }
    __syncthreads();
    if (threadIdx.x == 0) g_mask_u8 = found;
}

// ---------------- stage 1: gather + attention pooling + feature sum ----
__global__ void stage1_kernel(const int* __restrict__ x,
                              const unsigned char* __restrict__ xmask,
                              const float* __restrict__ xfeat,
                              const float* __restrict__ emb,
                              const float* __restrict__ attn_w,
                              const float* __restrict__ attn_b) {
    extern __shared__ float sm[];
    float* e_s     = sm;
    float* score_s = sm + T_ * H_;
    float* alpha_s = score_s + 64;

    int bs = blockIdx.x;
    int b = bs / S_, s = bs % S_;
    int tid = threadIdx.x, warp = tid >> 5, lane = tid & 31;
    int u8 = g_mask_u8;
    long base = (long)(b * S_ + s) * T_;
    float ab = attn_b[0];

    for (int t = warp; t < T_; t += 8) {
        int xi = x[base + t];
        long mi = base + t;
        unsigned char mv = u8 ? xmask[mi] : xmask[mi * 4];
        int valid = (mv == 0);
        float4 v0, v1;
        if (valid) {
            const float4* er = (const float4*)(emb + (long)xi * H_);
            v0 = er[lane]; v1 = er[lane + 32];
        } else {
            v0 = make_float4(0.f, 0.f, 0.f, 0.f); v1 = v0;
        }
        float4* ed = (float4*)(e_s + t * H_);
        ed[lane] = v0; ed[lane + 32] = v1;
        const float4* aw = (const float4*)attn_w;
        float4 w0 = aw[lane], w1 = aw[lane + 32];
        float p = v0.x*w0.x + v0.y*w0.y + v0.z*w0.z + v0.w*w0.w
                + v1.x*w1.x + v1.y*w1.y + v1.z*w1.z + v1.w*w1.w;
        #pragma unroll
        for (int o = 16; o; o >>= 1) p += __shfl_xor_sync(0xffffffffu, p, o);
        if (lane == 0) score_s[t] = valid ? (p + ab) : -1e30f;
    }
    __syncthreads();

    if (warp == 0) {
        float s0 = (lane < T_)      ? score_s[lane]      : -1e30f;
        float s1 = (lane + 32 < T_) ? score_s[lane + 32] : -1e30f;
        float mx = fmaxf(s0, s1);
        #pragma unroll
        for (int o = 16; o; o >>= 1) mx = fmaxf(mx, __shfl_xor_sync(0xffffffffu, mx, o));
        float e0 = (s0 > -1e29f) ? expf(s0 - mx) : 0.f;
        float e1 = (s1 > -1e29f) ? expf(s1 - mx) : 0.f;
        float sum = e0 + e1;
        #pragma unroll
        for (int o = 16; o; o >>= 1) sum += __shfl_xor_sync(0xffffffffu, sum, o);
        float inv = (mx > -1e29f) ? (1.f / sum) : 0.f;
        if (lane < T_)      alpha_s[lane]      = e0 * inv;
        if (lane + 32 < T_) alpha_s[lane + 32] = e1 * inv;
    }
    __syncthreads();

    float acc = 0.f;
    #pragma unroll 4
    for (int t = 0; t < T_; t++) acc += alpha_s[t] * e_s[t * H_ + tid];
    g_sen[(b * S_ + s) * DIN + tid] = acc;

    if (tid < F_) {
        float fa = 0.f;
        const float* fp = xfeat + base * F_ + tid;
        #pragma unroll 4
        for (int t = 0; t < T_; t++)
            if (score_s[t] > -1e29f) fa += fp[t * F_];
        g_sen[(b * S_ + s) * DIN + H_ + tid] = fa;
    }
}

// ---------------- XW GEMM (f32x2) with early-exit of padded M-tiles --------
// XW[dir][m][n] = sen[m]·wih[n] + bih[n] + bhh[n],  m = b*S + s
__global__ void __launch_bounds__(256) xw_gemm_kernel(
    const float* __restrict__ wf, const float* __restrict__ wb,
    const float* __restrict__ bih_f, const float* __restrict__ bhh_f,
    const float* __restrict__ bih_b, const float* __restrict__ bhh_b,
    const int* __restrict__ lens) {
    int m0 = blockIdx.x * 64;
    {
        bool anyact = false;
        #pragma unroll 8
        for (int mm = 0; mm < 64; mm++) {
            int m = m0 + mm;
            if ((m % S_) < lens[m / S_]) { anyact = true; break; }
        }
        if (!anyact) return;
    }
    const int PA = 33;   // As row pad
    const int PB = 68;   // Bst row pad (transposed [k][n])
    __shared__ float As[64 * PA];
    __shared__ float Bst[32 * PB];
    int dir = blockIdx.z;
    const float* A  = g_sen;
    const float* W  = dir ? wb : wf;
    const float* b1 = dir ? bih_b : bih_f;
    const float* b2 = dir ? bhh_b : bhh_f;
    int n0 = blockIdx.y * 64;
    int tid = threadIdx.x;
    int tx = tid & 15, ty = tid >> 4;      // cols [n0+4tx, +4), rows ty+16i

    unsigned long long acc[4][2];
    #pragma unroll
    for (int i = 0; i < 4; i++) { acc[i][0] = 0ull; acc[i][1] = 0ull; }

    for (int kt = 0; kt < DIN; kt += 32) {
        #pragma unroll
        for (int l = 0; l < 2; l++) {
            int f4 = tid + l * 256;
            int r = f4 >> 3, k4 = f4 & 7;
            float4 va = *(const float4*)(A + (long)(m0 + r) * DIN + kt + k4 * 4);
            float4 vb = *(const float4*)(W + (long)(n0 + r) * DIN + kt + k4 * 4);
            int so = r * PA + k4 * 4;
            As[so] = va.x; As[so + 1] = va.y; As[so + 2] = va.z; As[so + 3] = va.w;
            Bst[(k4 * 4 + 0) * PB + r] = vb.x;
            Bst[(k4 * 4 + 1) * PB + r] = vb.y;
            Bst[(k4 * 4 + 2) * PB + r] = vb.z;
            Bst[(k4 * 4 + 3) * PB + r] = vb.w;
        }
        __syncthreads();
        #pragma unroll
        for (int kk = 0; kk < 32; kk++) {
            const ulonglong2 bv = *(const ulonglong2*)(Bst + kk * PB + tx * 4);
            #pragma unroll
            for (int i = 0; i < 4; i++) {
                float a = As[(ty + 16 * i) * PA + kk];
                unsigned long long ap = packf2(a, a);
                acc[i][0] = fma2(ap, bv.x, acc[i][0]);
                acc[i][1] = fma2(ap, bv.y, acc[i][1]);
            }
        }
        __syncthreads();
    }
    float bs0 = b1[n0 + 4*tx]     + b2[n0 + 4*tx];
    float bs1 = b1[n0 + 4*tx + 1] + b2[n0 + 4*tx + 1];
    float bs2 = b1[n0 + 4*tx + 2] + b2[n0 + 4*tx + 2];
    float bs3 = b1[n0 + 4*tx + 3] + b2[n0 + 4*tx + 3];
    float* C = g_XW[dir];
    #pragma unroll
    for (int i = 0; i < 4; i++) {
        int m = m0 + ty + 16 * i;
        float c0, c1, c2, c3;
        unpackf2(acc[i][0], c0, c1);
        unpackf2(acc[i][1], c2, c3);
        *(float4*)(C + (long)m * GH + n0 + 4 * tx) =
            make_float4(c0 + bs0, c1 + bs1, c2 + bs2, c3 + bs3);
    }
}

// ---------------- clustered bidirectional LSTM recurrence ----------------
__device__ __forceinline__ float sigf(float x) { return 1.f / (1.f + expf(-x)); }

// 128 CTAs = 16 clusters of 8. Cluster = (dir, batch-group of 4 batches).
// CTA rank r owns hidden units [32r, 32r+32) (all 4 gates -> 128 Whh rows, 128KB smem).
// h lives in every CTA's smem, layout [buf][khalf][k:128][b:4] (+pad), exchanged
// each step via st.shared::cluster; one barrier.cluster per step.
// smem plan (floats): w_s[128*260]=33280 | h_s[2*1040]=2080 | g_sw[8*64]=512
#define LS_W   (128 * 260)
#define LS_H   (2 * 1040)
#define LS_TOT (LS_W + LS_H + 8 * 64)

__global__ void __launch_bounds__(256, 1) __cluster_dims__(CLUSTER, 1, 1)
lstm_kernel(const float* __restrict__ whh_f, const float* __restrict__ whh_b,
            const int* __restrict__ lens) {
    extern __shared__ float sm[];
    float* w_s  = sm;                 // [128][260]
    float* h_s  = sm + LS_W;          // [2][2][128][4] padded: off = p*1040 + kh*520 + k*4 + b
    float* g_sw = sm + LS_W + LS_H;   // [8 warps][16 rows][4 b]

    int dir  = blockIdx.x >> 6;
    int bg   = (blockIdx.x >> 3) & 7;
    int rank;
    asm("mov.u32 %0, %%cluster_ctarank;" : "=r"(rank));
    int tid = threadIdx.x, lane = tid & 31, warp = tid >> 5;
    const float* whh = dir ? whh_b : whh_f;

    // load this CTA's 128 Whh rows: row = warp*16 + gate*4 + uj
    for (int i = tid; i < 128 * 256; i += 256) {
        int row = i >> 8, k = i & 255;
        int wp = row >> 4, gate = (row >> 2) & 3, uj = row & 3;
        int gu = 32 * rank + 4 * wp + uj;
        w_s[row * 260 + k] = whh[(gate * H_ + gu) * H_ + k];
    }
    for (int i = tid; i < LS_H; i += 256) h_s[i] = 0.f;

    int khalf = lane >> 4, lr = lane & 15;
    const float* wp_ptr = w_s + (warp * 16 + lr) * 260 + khalf * 128;
    int len_grp = lens[bg * 4];                 // group max (lens sorted desc)
    // epilogue identity (lanes 0..15): uj = lr>>2 is NOT it; epilogue uses lane = uj*4+bi
    int e_uj = lane >> 2, e_bi = lane & 3;
    int e_gu = 32 * rank + 4 * warp + e_uj;
    int e_len = lens[bg * 4 + e_bi];
    float c_reg = 0.f;
    // gate-row identity for compute lanes (khalf==0 -> lane==lr)
    int grow = ((lr >> 2) * H_) + 32 * rank + 4 * warp + (lr & 3);
    const float* XWd = g_XW[dir];

    // precompute DSMEM peer base addresses of h_s
    uint32_t hs_base = smem_u32(h_s);
    uint32_t peer_base[CLUSTER];
    #pragma unroll
    for (int pr = 0; pr < CLUSTER; pr++) peer_base[pr] = mapa_u32(hs_base, pr);

    CLUSTER_SYNC();   // h_s zero-init visible cluster-wide before any step

    for (int t = 0; t < S_; t++) {
        int s = dir ? (S_ - 1 - t) : t;
        int p = t & 1;
        bool act = (s < len_grp);

        unsigned long long acc01 = 0ull, acc23 = 0ull;
        unsigned long long xw01 = 0ull, xw23 = 0ull;
        if (act && khalf == 0) {
            long xb = ((long)(bg * 4) * S_ + s) * GH + grow;
            float x0 = XWd[xb];
            float x1 = XWd[xb + (long)S_ * GH];
            float x2 = XWd[xb + 2L * S_ * GH];
            float x3 = XWd[xb + 3L * S_ * GH];
            xw01 = packf2(x0, x1); xw23 = packf2(x2, x3);
        }
        if (act) {
            const float* hp = h_s + p * 1040 + khalf * 520;
            #pragma unroll 8
            for (int k = 0; k < 128; k += 4) {
                float4 wv = *(const float4*)(wp_ptr + k);
                ulonglong2 h0 = *(const ulonglong2*)(hp + k * 4);
                ulonglong2 h1 = *(const ulonglong2*)(hp + k * 4 + 4);
                ulonglong2 h2 = *(const ulonglong2*)(hp + k * 4 + 8);
                ulonglong2 h3 = *(const ulonglong2*)(hp + k * 4 + 12);
                acc01 = fma2(packf2(wv.x, wv.x), h0.x, acc01);
                acc23 = fma2(packf2(wv.x, wv.x), h0.y, acc23);
                acc01 = fma2(packf2(wv.y, wv.y), h1.x, acc01);
                acc23 = fma2(packf2(wv.y, wv.y), h1.y, acc23);
                acc01 = fma2(packf2(wv.z, wv.z), h2.x, acc01);
                acc23 = fma2(packf2(wv.z, wv.z), h2.y, acc23);
                acc01 = fma2(packf2(wv.w, wv.w), h3.x, acc01);
                acc23 = fma2(packf2(wv.w, wv.w), h3.y, acc23);
            }
            acc01 = addf2(acc01, __shfl_xor_sync(0xffffffffu, acc01, 16));
            acc23 = addf2(acc23, __shfl_xor_sync(0xffffffffu, acc23, 16));
            if (khalf == 0) {
                *(unsigned long long*)(g_sw + warp * 64 + lr * 4)     = addf2(acc01, xw01);
                *(unsigned long long*)(g_sw + warp * 64 + lr * 4 + 2) = addf2(acc23, xw23);
            }
        }
        __syncwarp();

        if (lane < 16) {
            int hoff_cur = p * 1040 + (e_gu >> 7) * 520 + (e_gu & 127) * 4 + e_bi;
            float hn = h_s[hoff_cur];
            if (act) {
                const float* gw = g_sw + warp * 64;
                float gi = gw[(0 * 4 + e_uj) * 4 + e_bi];
                float gf = gw[(1 * 4 + e_uj) * 4 + e_bi];
                float gg = gw[(2 * 4 + e_uj) * 4 + e_bi];
                float go = gw[(3 * 4 + e_uj) * 4 + e_bi];
                float c2 = sigf(gf) * c_reg + sigf(gi) * tanhf(gg);
                float h2 = sigf(go) * tanhf(c2);
                if (s < e_len) { c_reg = c2; hn = h2; }
            }
            uint32_t off4 = (uint32_t)(((p ^ 1) * 1040 + (e_gu >> 7) * 520 +
                                        (e_gu & 127) * 4 + e_bi) * 4);
            #pragma unroll
            for (int pr = 0; pr < CLUSTER; pr++)
                st_cluster_f32(peer_base[pr] + off4, hn);
            if (t == S_ - 1) g_hfinal[dir][bg * 4 + e_bi][e_gu] = hn;
        }
        CLUSTER_SYNC();   // release my DSMEM stores / acquire peers'
    }
}

// ---------------- FC + BN(batch axis) + relu + log_softmax(batch axis) ----
__global__ void final_kernel(const float* __restrict__ fc_w, const float* __restrict__ fc_b,
                             const float* __restrict__ gamma, const float* __restrict__ beta,
                             float* __restrict__ out) {
    __shared__ float wsh[2 * H_];
    __shared__ float lg[B_];
    int j = blockIdx.x;
    int tid = threadIdx.x, warp = tid >> 5, lane = tid & 31;
    for (int i = tid; i < 2 * H_; i += 256) wsh[i] = fc_w[j * 2 * H_ + i];
    __syncthreads();

    #pragma unroll
    for (int ii = 0; ii < 4; ii++) {
        int i = warp * 4 + ii;
        int dirc = i >> 4;
        int bb = (i & 15) * 2;
        const float* h0 = g_hfinal[dirc][bb];
        const float* h1 = g_hfinal[dirc][bb + 1];
        float p = 0.f;
        for (int k = lane; k < H_; k += 32) p += h0[k] * wsh[k] + h1[k] * wsh[H_ + k];
        #pragma unroll
        for (int o = 16; o; o >>= 1) p += __shfl_xor_sync(0xffffffffu, p, o);
        if (lane == 0) lg[i] = p + fc_b[j];
    }
    __syncthreads();

    if (warp == 0) {
        float v = lg[lane];
        float sum = v;
        #pragma unroll
        for (int o = 16; o; o >>= 1) sum += __shfl_xor_sync(0xffffffffu, sum, o);
        float mu = sum * (1.f / 32.f);
        float d = v - mu;
        float vs = d * d;
        #pragma unroll
        for (int o = 16; o; o >>= 1) vs += __shfl_xor_sync(0xffffffffu, vs, o);
        float var = vs * (1.f / 32.f);
        float y = gamma[j] * d * rsqrtf(var + 1e-5f) + beta[j];
        y = fmaxf(y, 0.f);
        float mx = y;
        #pragma unroll
        for (int o = 16; o; o >>= 1) mx = fmaxf(mx, __shfl_xor_sync(0xffffffffu, mx, o));
        float ev = expf(y - mx);
        float se = ev;
        #pragma unroll
        for (int o = 16; o; o >>= 1) se += __shfl_xor_sync(0xffffffffu, se, o);
        out[lane * OUTD + j] = y - mx - logf(se);
    }
}

// ---------------- launch ----------------
extern "C" void kernel_launch(void* const* d_in, const int* in_sizes, int n_in,
                              void* d_out, int out_size) {
    const int*           x      = (const int*)d_in[0];
    const unsigned char* xmask  = (const unsigned char*)d_in[1];
    const float*         xfeat  = (const float*)d_in[2];
    const int*           lens   = (const int*)d_in[3];
    const float* emb    = (const float*)d_in[6];
    const float* attn_w = (const float*)d_in[7];
    const float* attn_b = (const float*)d_in[8];
    const float* wih_f  = (const float*)d_in[9];
    const float* whh_f  = (const float*)d_in[10];
    const float* bih_f  = (const float*)d_in[11];
    const float* bhh_f  = (const float*)d_in[12];
    const float* wih_b  = (const float*)d_in[13];
    const float* whh_b  = (const float*)d_in[14];
    const float* bih_b  = (const float*)d_in[15];
    const float* bhh_b  = (const float*)d_in[16];
    const float* fc_w   = (const float*)d_in[17];
    const float* fc_b   = (const float*)d_in[18];
    const float* bn_g   = (const float*)d_in[19];
    const float* bn_b   = (const float*)d_in[20];

    const int smem1 = (T_ * H_ + 128) * 4;
    const int smemL = LS_TOT * 4;    // ~143.5 KB
    cudaFuncSetAttribute(stage1_kernel, cudaFuncAttributeMaxDynamicSharedMemorySize, smem1);
    cudaFuncSetAttribute(lstm_kernel,   cudaFuncAttributeMaxDynamicSharedMemorySize, smemL);

    detect_mask_kernel<<<1, 256>>>((const uint4*)xmask, (B_ * S_ * T_) / 16);
    stage1_kernel<<<B_ * S_, 256, smem1>>>(x, xmask, xfeat, emb, attn_w, attn_b);
    xw_gemm_kernel<<<dim3(B_ * S_ / 64, GH / 64, 2), 256>>>(wih_f, wih_b, bih_f, bhh_f,
                                                            bih_b, bhh_b, lens);
    lstm_kernel<<<128, 256, smemL>>>(whh_f, whh_b, lens);
    final_kernel<<<OUTD, 256>>>(fc_w, fc_b, bn_g, bn_b, (float*)d_out);
}